// round 5
// baseline (speedup 1.0000x reference)
#include <cuda_runtime.h>

#define B 8
#define P 2048
#define D 1024
#define E 16
#define S 64
#define DK 128
#define H 16

typedef unsigned long long ull;

// ---------------- scratch (static device globals; no allocation) ----------------
__device__ float g_mu[B * P];
__device__ float g_rs[B * P];
__device__ float g_V[(size_t)B * P * 2 * DK];   // per-(token,slot) V vectors (16 MB)
__device__ float g_q[B * P * 2];                // per-(token,slot) V . dsum
__device__ float g_we[E];
__device__ float g_aw[E];
__device__ float g_invt;
__device__ float g_dsum[E * DK];                // sum over 5 normalized penta dirs
__device__ int   g_cnt[E];
__device__ int   g_list[E * P];                 // p | (slot<<16)
__device__ int   g_pe[P * 2];                   // active experts per p (-1 = none)
__device__ float g_den[P];

// ---------------- f32x2 packed-FMA helpers ----------------
__device__ __forceinline__ ull pk2(float lo, float hi) {
    ull r;
    asm("mov.b64 %0, {%1, %2};" : "=l"(r) : "f"(lo), "f"(hi));
    return r;
}
__device__ __forceinline__ void fma2(ull &c, ull a, ull b) {
    asm("fma.rn.f32x2 %0, %1, %2, %3;" : "=l"(c) : "l"(a), "l"(b), "l"(c));
}
__device__ __forceinline__ float2 upk2(ull v) {
    float lo, hi;
    asm("mov.b64 {%0, %1}, %2;" : "=f"(lo), "=f"(hi) : "l"(v));
    return make_float2(lo, hi);
}

__device__ __forceinline__ float sigmf(float x) { return 1.0f / (1.0f + expf(-x)); }

// ---------------- K0: scalars + dsum + binning (one block) ----------------
__global__ void k_init(const float* __restrict__ alpha, const float* __restrict__ betas,
                       const float* __restrict__ pos_embed, const float* __restrict__ penta,
                       const float* __restrict__ temp, const float* __restrict__ fps) {
    __shared__ float rn[E * 5];
    int t = threadIdx.x;
    if (t < E) {
        g_cnt[t] = 0;
        g_aw[t] = sigmf(alpha[t]);
        float s = 0.0f;
        for (int d = 0; d < DK; d++) s += pos_embed[t * DK + d];
        float pw = sigmf(s * (1.0f / DK));
        const int offs[4] = {-2, -1, 1, 2};
        float vw = 0.0f; int vc = 0;
        for (int j = 0; j < 4; j++) {
            int nb = t + offs[j];
            if (nb >= 0 && nb < E) { vw += sigmf(betas[t * 4 + j]); vc++; }
        }
        g_we[t] = pw * (1.0f + vw / (float)vc);
    }
    if (t == 0) g_invt = 1.0f / fabsf(temp[0]);
    if (t < E * 5) {
        const float* row = penta + (size_t)t * DK;
        float ss = 0.0f;
        for (int d = 0; d < DK; d++) ss += row[d] * row[d];
        rn[t] = rsqrtf(ss);
    }
    __syncthreads();
    for (int i = t; i < E * DK; i += blockDim.x) {
        int e = i >> 7, d = i & 127;
        float s = 0.0f;
#pragma unroll
        for (int v = 0; v < 5; v++) s += penta[(e * 5 + v) * DK + d] * rn[e * 5 + v];
        g_dsum[i] = s;
    }
    for (int p = t; p < P; p += blockDim.x) {
        float fp = fps[p];
        int e0 = -1, e1 = -1;
        float den = 0.0f;
        for (int e = 0; e < E; e++) {
            float mn = fmaxf(0.0f, e * 0.0625f - 0.03125f);
            float mx = fminf(1.0f, (e + 1) * 0.0625f + 0.03125f);
            if (fp >= mn && fp < mx) {
                den += g_we[e];
                int slot;
                if (e0 < 0) { e0 = e; slot = 0; } else { e1 = e; slot = 1; }
                int pos = atomicAdd(&g_cnt[e], 1);
                g_list[e * P + pos] = p | (slot << 16);
            }
        }
        g_pe[p * 2] = e0;
        g_pe[p * 2 + 1] = e1;
        g_den[p] = fmaxf(den, 1e-6f);
    }
}

// ---------------- K1: layernorm stats + residual copy ----------------
__global__ void __launch_bounds__(256) k_ln(const float* __restrict__ x,
                                            float* __restrict__ out) {
    int warp = threadIdx.x >> 5, lane = threadIdx.x & 31;
    int tok = blockIdx.x * 8 + warp;
    const float4* xr = (const float4*)(x + (size_t)tok * D);
    float4 v[8];
    float sum = 0.0f;
#pragma unroll
    for (int k = 0; k < 8; k++) {
        v[k] = xr[k * 32 + lane];
        sum += v[k].x + v[k].y + v[k].z + v[k].w;
    }
#pragma unroll
    for (int o = 16; o; o >>= 1) sum += __shfl_xor_sync(0xffffffffu, sum, o);
    float mu = sum * (1.0f / D);
    float vs = 0.0f;
#pragma unroll
    for (int k = 0; k < 8; k++) {
        float dx = v[k].x - mu, dy = v[k].y - mu, dz = v[k].z - mu, dw = v[k].w - mu;
        vs += dx * dx + dy * dy + dz * dz + dw * dw;
    }
#pragma unroll
    for (int o = 16; o; o >>= 1) vs += __shfl_xor_sync(0xffffffffu, vs, o);
    float rstd = rsqrtf(vs * (1.0f / D) + 1e-5f);

    float4* orow = (float4*)(out + (size_t)tok * D);
#pragma unroll
    for (int k = 0; k < 8; k++) orow[k * 32 + lane] = v[k];
    if (lane == 0) { g_mu[tok] = mu; g_rs[tok] = rstd; }
}

// ---------------- K2: gate + V GEMM + projection scalar (64-row tiles) ----------------
// smem floats: aTd 8192 | Ws 8192 | w1s 1024 | gb 128 | dss 128 | gs 64 = 17728
__global__ void __launch_bounds__(256, 3)
k_gatev(const float* __restrict__ x, const float* __restrict__ gamma,
        const float* __restrict__ beta, const float* __restrict__ w1,
        const float* __restrict__ b1, const float* __restrict__ w2,
        const float* __restrict__ b2, const float* __restrict__ wv) {
    int e = blockIdx.y;
    int cnt = g_cnt[e];
    int base = blockIdx.x * 8;
    if (base >= cnt) return;

    extern __shared__ float sm[];
    float* aTd = sm;              // [s][2*row] duplicated, 64*128
    float* Ws  = sm + 8192;       // [s][col], 64*128
    float* w1s = sm + 16384;      // 64*16
    float* gb  = sm + 17408;      // gamma 64 | beta 64
    float* dss = sm + 17536;      // 128
    float* gs  = sm + 17664;      // 64
    __shared__ int sp[8], ssl[8];
    int tid = threadIdx.x;

    if (tid < 8) {
        int idx = base + tid;
        if (idx < cnt) {
            int v = g_list[e * P + idx];
            sp[tid] = v & 0xFFFF; ssl[tid] = v >> 16;
        } else { sp[tid] = -1; ssl[tid] = 0; }
    }
    {
        const float4* src = (const float4*)(wv + (size_t)e * S * DK);
        float4* dst = (float4*)Ws;
#pragma unroll
        for (int k = 0; k < 8; k++) dst[tid + k * 256] = src[tid + k * 256];
        ((float4*)w1s)[tid] = ((const float4*)(w1 + (size_t)e * S * H))[tid];
    }
    if (tid < 16)                 ((float4*)gb)[tid]        = ((const float4*)gamma)[e * 16 + tid];
    else if (tid < 32)            ((float4*)(gb + 64))[tid - 16] = ((const float4*)beta)[e * 16 + (tid - 16)];
    else if (tid < 64)            ((float4*)dss)[tid - 32]  = ((const float4*)(g_dsum + e * DK))[tid - 32];
    __syncthreads();

    // stage A (apply LN on the fly), duplicated per row
    {
        int r = tid >> 2, q = tid & 3;
        int p = sp[r >> 3];
        ull* dst = (ull*)aTd;      // index s*64 + r
        if (p >= 0) {
            int b = r & 7;
            int tok = b * P + p;
            float mu = g_mu[tok], rs = g_rs[tok];
            const float4* src = (const float4*)(x + (size_t)tok * D + e * S) + q * 4;
            const float4* gm4 = (const float4*)gb + q * 4;
            const float4* bt4 = (const float4*)(gb + 64) + q * 4;
#pragma unroll
            for (int k = 0; k < 4; k++) {
                float4 v = src[k], g4 = gm4[k], b4 = bt4[k];
                int s0 = q * 16 + k * 4;
                float f0 = (v.x - mu) * rs * g4.x + b4.x;
                float f1 = (v.y - mu) * rs * g4.y + b4.y;
                float f2 = (v.z - mu) * rs * g4.z + b4.z;
                float f3 = (v.w - mu) * rs * g4.w + b4.w;
                dst[(s0 + 0) * 64 + r] = pk2(f0, f0);
                dst[(s0 + 1) * 64 + r] = pk2(f1, f1);
                dst[(s0 + 2) * 64 + r] = pk2(f2, f2);
                dst[(s0 + 3) * 64 + r] = pk2(f3, f3);
            }
        } else {
#pragma unroll
            for (int k = 0; k < 16; k++) dst[(q * 16 + k) * 64 + r] = 0ull;
        }
    }
    __syncthreads();

    // alpha gate: 4 threads per row, 16 k-steps each, shfl-reduce
    {
        int r = tid >> 2, q = tid & 3;
        float h[H];
#pragma unroll
        for (int j = 0; j < H; j++) h[j] = 0.0f;
        for (int s = q * 16; s < q * 16 + 16; s++) {
            float av = aTd[s * 128 + 2 * r];
            const float4* wr = (const float4*)(w1s + s * H);
            float4 q0 = wr[0], q1 = wr[1], q2 = wr[2], q3 = wr[3];
            h[0]  += av * q0.x; h[1]  += av * q0.y; h[2]  += av * q0.z; h[3]  += av * q0.w;
            h[4]  += av * q1.x; h[5]  += av * q1.y; h[6]  += av * q1.z; h[7]  += av * q1.w;
            h[8]  += av * q2.x; h[9]  += av * q2.y; h[10] += av * q2.z; h[11] += av * q2.w;
            h[12] += av * q3.x; h[13] += av * q3.y; h[14] += av * q3.z; h[15] += av * q3.w;
        }
#pragma unroll
        for (int j = 0; j < H; j++) {
            h[j] += __shfl_xor_sync(0xffffffffu, h[j], 1);
            h[j] += __shfl_xor_sync(0xffffffffu, h[j], 2);
        }
        if (q == 0) {
            float gacc = b2[e];
#pragma unroll
            for (int j = 0; j < H; j++) {
                float hv = h[j] + b1[e * H + j];
                float ge = 0.5f * hv * (1.0f + erff(hv * 0.70710678118654752f));
                gacc += ge * w2[e * H + j];
            }
            float aw = g_aw[e];
            gs[r] = sigmf(gacc) * aw + (1.0f - aw);
        }
    }
    __syncthreads();

    // GEMM: C[64,128] = A[64,64] @ Ws[64,128]
    int R = tid >> 4, Cg = tid & 15;   // rows 4R..4R+3, cols Cg*4..+3 and 64+Cg*4..+3
    ull acc[4][4];
#pragma unroll
    for (int i = 0; i < 4; i++)
#pragma unroll
        for (int j = 0; j < 4; j++) acc[i][j] = 0ull;

    const ulonglong2* A2 = (const ulonglong2*)aTd;  // 32 per s-row
    const ulonglong2* W2 = (const ulonglong2*)Ws;   // 32 per s-row
#pragma unroll 4
    for (int s = 0; s < S; s++) {
        ulonglong2 alo = A2[s * 32 + 2 * R];
        ulonglong2 ahi = A2[s * 32 + 2 * R + 1];
        ulonglong2 wl  = W2[s * 32 + Cg];
        ulonglong2 wh  = W2[s * 32 + 16 + Cg];
        fma2(acc[0][0], alo.x, wl.x); fma2(acc[0][1], alo.x, wl.y);
        fma2(acc[0][2], alo.x, wh.x); fma2(acc[0][3], alo.x, wh.y);
        fma2(acc[1][0], alo.y, wl.x); fma2(acc[1][1], alo.y, wl.y);
        fma2(acc[1][2], alo.y, wh.x); fma2(acc[1][3], alo.y, wh.y);
        fma2(acc[2][0], ahi.x, wl.x); fma2(acc[2][1], ahi.x, wl.y);
        fma2(acc[2][2], ahi.x, wh.x); fma2(acc[2][3], ahi.x, wh.y);
        fma2(acc[3][0], ahi.y, wl.x); fma2(acc[3][1], ahi.y, wl.y);
        fma2(acc[3][2], ahi.y, wh.x); fma2(acc[3][3], ahi.y, wh.y);
    }

    // epilogue: scale by gate, store V, compute q = V . dsum
    int entry = R >> 1;
    int p = sp[entry];
    float4 dlo = ((const float4*)dss)[Cg];
    float4 dhi = ((const float4*)dss)[16 + Cg];
    float ps[4];
#pragma unroll
    for (int i = 0; i < 4; i++) {
        int r = 4 * R + i;
        float g = gs[r];
        float2 c0 = upk2(acc[i][0]), c1 = upk2(acc[i][1]);
        float2 c2 = upk2(acc[i][2]), c3 = upk2(acc[i][3]);
        float v0 = c0.x * g, v1 = c0.y * g, v2 = c1.x * g, v3 = c1.y * g;
        float v4 = c2.x * g, v5 = c2.y * g, v6 = c3.x * g, v7 = c3.y * g;
        ps[i] = v0 * dlo.x + v1 * dlo.y + v2 * dlo.z + v3 * dlo.w
              + v4 * dhi.x + v5 * dhi.y + v6 * dhi.z + v7 * dhi.w;
        if (p >= 0) {
            int b = r & 7, sl = ssl[entry];
            float* dst = g_V + ((((size_t)(b * P + p)) * 2 + sl) * DK);
            *(float4*)(dst + Cg * 4)      = make_float4(v0, v1, v2, v3);
            *(float4*)(dst + 64 + Cg * 4) = make_float4(v4, v5, v6, v7);
        }
    }
#pragma unroll
    for (int i = 0; i < 4; i++) {
        ps[i] += __shfl_xor_sync(0xffffffffu, ps[i], 1);
        ps[i] += __shfl_xor_sync(0xffffffffu, ps[i], 2);
        ps[i] += __shfl_xor_sync(0xffffffffu, ps[i], 4);
        ps[i] += __shfl_xor_sync(0xffffffffu, ps[i], 8);
    }
    if (Cg == 0 && p >= 0) {
        int sl = ssl[entry];
#pragma unroll
        for (int i = 0; i < 4; i++) {
            int r = 4 * R + i, b = r & 7;
            g_q[(size_t)(b * P + p) * 2 + sl] = ps[i];
        }
    }
}

// ---------------- K3: rec GEMM (64-row tiles), out = x + f*rec ----------------
// smem floats: Vtd 16384 | Ws 8192 | fs 64 = 24640
__global__ void __launch_bounds__(256, 2)
k_rec(const float* __restrict__ x, const float* __restrict__ wout,
      float* __restrict__ out) {
    int e = blockIdx.y;
    int cnt = g_cnt[e];
    int base = blockIdx.x * 8;
    if (base >= cnt) return;

    extern __shared__ float sm[];
    float* Vtd = sm;              // [d][2*row] duplicated, 128*128
    float* Ws  = sm + 16384;      // [d][col], 128*64
    float* fs  = sm + 24576;      // 64
    __shared__ int sp[8], ssl[8];
    int tid = threadIdx.x;

    if (tid < 8) {
        int idx = base + tid;
        if (idx < cnt) {
            int v = g_list[e * P + idx];
            sp[tid] = v & 0xFFFF; ssl[tid] = v >> 16;
        } else { sp[tid] = -1; ssl[tid] = 0; }
    }
    {
        const float4* src = (const float4*)(wout + (size_t)e * DK * S);
        float4* dst = (float4*)Ws;
#pragma unroll
        for (int k = 0; k < 8; k++) dst[tid + k * 256] = src[tid + k * 256];
    }
    __syncthreads();

    if (tid < 64) {
        int entry = tid >> 3;
        int p = sp[entry];
        float f = 0.0f;
        if (p >= 0) {
            int b = tid & 7;
            int tok = b * P + p;
            int e0 = g_pe[2 * p], e1 = g_pe[2 * p + 1];
            float s = 0.0f;
            if (e0 >= 0) s += g_we[e0] * g_q[(size_t)tok * 2];
            if (e1 >= 0) s += g_we[e1] * g_q[(size_t)tok * 2 + 1];
            f = s * 0.2f * g_invt / g_den[p];
        }
        fs[tid] = f;
    }
    // stage V transposed + duplicated
    {
        int r = tid >> 2, q = tid & 3;
        int p = sp[r >> 3];
        ull* dst = (ull*)Vtd;      // index d*64 + r
        if (p >= 0) {
            int b = r & 7, sl = ssl[r >> 3];
            const float4* src = (const float4*)(g_V + (((size_t)(b * P + p)) * 2 + sl) * DK) + q * 8;
#pragma unroll
            for (int k = 0; k < 8; k++) {
                float4 v = src[k];
                int d0 = q * 32 + k * 4;
                dst[(d0 + 0) * 64 + r] = pk2(v.x, v.x);
                dst[(d0 + 1) * 64 + r] = pk2(v.y, v.y);
                dst[(d0 + 2) * 64 + r] = pk2(v.z, v.z);
                dst[(d0 + 3) * 64 + r] = pk2(v.w, v.w);
            }
        } else {
#pragma unroll
            for (int k = 0; k < 32; k++) dst[(q * 32 + k) * 64 + r] = 0ull;
        }
    }
    __syncthreads();

    // GEMM: C[64,64] = V[64,128] @ Ws[128,64]
    int R = tid >> 4, Cg = tid & 15;   // rows 4R..4R+3, cols Cg*4..+3
    ull acc[4][2];
#pragma unroll
    for (int i = 0; i < 4; i++) { acc[i][0] = 0ull; acc[i][1] = 0ull; }

    const ulonglong2* A2 = (const ulonglong2*)Vtd;  // 32 per d-row
    const ulonglong2* W2 = (const ulonglong2*)Ws;   // 16 per d-row
#pragma unroll 4
    for (int d = 0; d < DK; d++) {
        ulonglong2 alo = A2[d * 32 + 2 * R];
        ulonglong2 ahi = A2[d * 32 + 2 * R + 1];
        ulonglong2 w   = W2[d * 16 + Cg];
        fma2(acc[0][0], alo.x, w.x); fma2(acc[0][1], alo.x, w.y);
        fma2(acc[1][0], alo.y, w.x); fma2(acc[1][1], alo.y, w.y);
        fma2(acc[2][0], ahi.x, w.x); fma2(acc[2][1], ahi.x, w.y);
        fma2(acc[3][0], ahi.y, w.x); fma2(acc[3][1], ahi.y, w.y);
    }

    int p = sp[R >> 1];
    if (p >= 0) {
#pragma unroll
        for (int i = 0; i < 4; i++) {
            int r = 4 * R + i, b = r & 7;
            float f = fs[r];
            size_t off = ((size_t)(b * P + p)) * D + e * S + Cg * 4;
            float4 xv = *(const float4*)(x + off);
            float2 c0 = upk2(acc[i][0]), c1 = upk2(acc[i][1]);
            *(float4*)(out + off) = make_float4(xv.x + f * c0.x, xv.y + f * c0.y,
                                                xv.z + f * c1.x, xv.w + f * c1.y);
        }
    }
}

// ---------------- launch ----------------
extern "C" void kernel_launch(void* const* d_in, const int* in_sizes, int n_in,
                              void* d_out, int out_size) {
    const float* x     = (const float*)d_in[0];
    const float* fps   = (const float*)d_in[1];
    const float* gamma = (const float*)d_in[2];
    const float* beta  = (const float*)d_in[3];
    const float* w1    = (const float*)d_in[4];
    const float* b1    = (const float*)d_in[5];
    const float* w2    = (const float*)d_in[6];
    const float* b2    = (const float*)d_in[7];
    const float* alpha = (const float*)d_in[8];
    const float* wv    = (const float*)d_in[9];
    const float* penta = (const float*)d_in[10];
    const float* betas = (const float*)d_in[11];
    const float* wout  = (const float*)d_in[12];
    const float* pos   = (const float*)d_in[13];
    const float* temp  = (const float*)d_in[14];
    float* out = (float*)d_out;

    const int gatev_smem = 17728 * (int)sizeof(float);   // ~69.25 KB
    const int rec_smem   = 24640 * (int)sizeof(float);   // ~96.25 KB
    static int attr_done = 0;
    if (!attr_done) {
        cudaFuncSetAttribute(k_gatev, cudaFuncAttributeMaxDynamicSharedMemorySize, gatev_smem);
        cudaFuncSetAttribute(k_rec,   cudaFuncAttributeMaxDynamicSharedMemorySize, rec_smem);
        attr_done = 1;
    }

    k_init<<<1, 1024>>>(alpha, betas, pos, penta, temp, fps);
    k_ln<<<(B * P) / 8, 256>>>(x, out);
    k_gatev<<<dim3(64, E), 256, gatev_smem>>>(x, gamma, beta, w1, b1, w2, b2, wv);
    k_rec<<<dim3(64, E), 256, rec_smem>>>(x, wout, out);
}